// round 17
// baseline (speedup 1.0000x reference)
#include <cuda_runtime.h>
#include <float.h>

// Problem constants
#define B      2
#define C      3
#define T      8
#define H      448
#define W      448
#define NKEY   4
#define L      196      // 14*14
#define GH     14
#define R      121      // 11*11
#define NS     500
#define BK     (B*NKEY) // 8
#define OUTHW  128      // s*A
#define ABPK   63       // argmax blocks per key

// Device scratch (no allocation allowed). All handshake state is 0 at module
// load and reset within the same launch that consumes it => replay-safe.
__device__ float g_scn[BK][R];   // normalized region scores
__device__ int   g_cnt[BK][R];   // top-1 histogram (zeroed by producer)
__device__ int   g_flag[BK];     // scorenorm-ready flags (reset by gather)
__device__ int   g_tick[BK];     // per-key completion tickets (reset by last block)
__device__ float g_wc[BK][R];    // compacted weights   (written by last block)
__device__ int   g_off[BK][R];   // compacted offsets
__device__ int   g_nnz[BK];

// ---------------------------------------------------------------------------
// Kernel 1: fused score-norm + perturbed top-1 argmax + tail compaction.
// grid = (63, 8), block = 256. Single wave => handshakes safe (R10-proven).
//   block x==0 per key: normalized scores -> g_scn, zero g_cnt, raise flag.
//   all blocks: one warp per sample, warp argmax, atomic histogram,
//     lane-0 __threadfence (release) before the ticket.
//   LAST block per key (ticket acquire): ballot-compact -> g_wc/g_off/g_nnz.
// ---------------------------------------------------------------------------
__global__ void argmax_kernel(const float* __restrict__ score,
                              const float* __restrict__ noise,
                              const float* __restrict__ sigma_p)
{
    const int bk   = blockIdx.y;
    const int tid  = threadIdx.x;
    const int lane = tid & 31;
    const int wrp  = tid >> 5;

    __shared__ float sc[R];
    __shared__ float wmin[4], wmax[4];
    __shared__ float lo_s, inv_s;
    __shared__ int   is_last;
    __shared__ int   wbase[4];

    if (blockIdx.x == 0) {
        // ---- producer: compute normalized scores once per key ----
        float v = 0.f;
        if (tid < R) {
            const int ri = tid / 11;
            const int rj = tid % 11;
            const float* sp = score + bk * L;
            #pragma unroll
            for (int ki = 0; ki < 4; ki++)
                #pragma unroll
                for (int kj = 0; kj < 4; kj++)
                    v += sp[(ri + ki) * GH + (rj + kj)];
            v *= (1.f / 16.f);
        }
        if (wrp < 4) {
            float mn = (tid < R) ? v : FLT_MAX;
            float mx = (tid < R) ? v : -FLT_MAX;
            #pragma unroll
            for (int o = 16; o > 0; o >>= 1) {
                mn = fminf(mn, __shfl_down_sync(0xffffffffu, mn, o));
                mx = fmaxf(mx, __shfl_down_sync(0xffffffffu, mx, o));
            }
            if (lane == 0) { wmin[wrp] = mn; wmax[wrp] = mx; }
        }
        __syncthreads();
        if (tid == 0) {
            float lo = fminf(fminf(wmin[0], wmin[1]), fminf(wmin[2], wmin[3]));
            float hi = fmaxf(fmaxf(wmax[0], wmax[1]), fmaxf(wmax[2], wmax[3]));
            lo_s  = lo;
            inv_s = 1.f / (hi - lo + 1e-5f);
        }
        __syncthreads();
        if (tid < R) {
            float nv = (v - lo_s) * inv_s;
            sc[tid] = nv;
            g_scn[bk][tid] = nv;
            g_cnt[bk][tid] = 0;
        }
        // release g_scn/g_cnt: every writer fences, then barrier, then flag
        __threadfence();
        __syncthreads();
        if (tid == 0) atomicExch(&g_flag[bk], 1);
    } else {
        // ---- consumer: wait for producer, then load normalized scores ----
        if (tid == 0) {
            while (atomicAdd(&g_flag[bk], 0) == 0) __nanosleep(32);
        }
        __syncthreads();
        if (tid < R) sc[tid] = __ldcg(&g_scn[bk][tid]);
        __syncthreads();
    }

    // ---- one warp per sample ----
    const int n = blockIdx.x * 8 + wrp;
    if (n < NS) {
        const float sigma = sigma_p[0];
        const float* nn = noise + ((size_t)bk * NS + n) * R;

        // warp argmax, first-max / lowest-index tie-break (lax.top_k)
        float best = -FLT_MAX;
        int   bi   = 0;
        #pragma unroll
        for (int j = 0; j < 4; j++) {
            int r = lane + 32 * j;
            if (r < R) {
                float p = fmaf(nn[r], sigma, sc[r]);
                if (p > best) { best = p; bi = r; }
            }
        }
        #pragma unroll
        for (int o = 16; o > 0; o >>= 1) {
            float v2 = __shfl_down_sync(0xffffffffu, best, o);
            int   i2 = __shfl_down_sync(0xffffffffu, bi,   o);
            if (v2 > best || (v2 == best && i2 < bi)) { best = v2; bi = i2; }
        }
        if (lane == 0) {
            atomicAdd(&g_cnt[bk][bi], 1);      // order-independent
            __threadfence();                   // RELEASE this add before ticket
        }
    }
    __syncthreads();

    // ---- ticket: last block of this key compacts the histogram ----
    if (tid == 0) {
        int old = atomicAdd(&g_tick[bk], 1);   // fences above + barrier => release
        is_last = (old == ABPK - 1);
    }
    __syncthreads();
    if (!is_last) return;

    __threadfence();                           // ACQUIRE all g_cnt updates

    // Ballot compaction (order-preserving => deterministic)
    int  cnt = (tid < R) ? __ldcg(&g_cnt[bk][tid]) : 0;
    bool p   = (cnt > 0);
    unsigned m = __ballot_sync(0xffffffffu, p);
    int within = __popc(m & ((1u << lane) - 1u));
    if (wrp < 4 && lane == 0) wbase[wrp] = __popc(m);
    __syncthreads();
    if (tid == 0) {
        int s = 0;
        #pragma unroll
        for (int w2 = 0; w2 < 4; w2++) { int tt = wbase[w2]; wbase[w2] = s; s += tt; }
        g_nnz[bk]  = s;
        g_tick[bk] = 0;                        // reset ticket for next launch
    }
    __syncthreads();                           // <-- BUG FIX: prefix before use
    if (p) {
        int pos = wbase[wrp] + within;
        g_wc[bk][pos]  = (float)cnt * (1.f / (float)NS);
        g_off[bk][pos] = (tid / 11) * 32 * W + (tid % 11) * 32;
    }
    // g_nnz/g_wc/g_off land before kernel end; next node (graph-ordered) sees them.
}

// ---------------------------------------------------------------------------
// Kernel 2: fused gather + weighted sum. One output row per warp, float4
// lanes, unroll-4 region loop (nnz is tiny, ~3). Minimal prologue: uniform
// nnz load + <=nnz smem fills + ONE barrier. 384 blocks x 512 threads
// (16 rows/block) => one wave.
// ---------------------------------------------------------------------------
__global__ __launch_bounds__(512, 4)
void gather_kernel(const float* __restrict__ x,
                   const int*   __restrict__ group_id,
                   float*       __restrict__ out)
{
    const int tid  = threadIdx.x;
    const int wrp  = tid >> 5;
    const int lane = tid & 31;

    // flag reset for next launch: exactly one block does it
    if (blockIdx.x == 0 && tid < BK) g_flag[tid] = 0;

    const int rowbase = blockIdx.x * 16;       // 16 rows share (b,c,t)
    const int rowhi   = rowbase >> 7;          // (b*3+c)*8 + t
    const int y       = (rowbase & (OUTHW - 1)) + wrp;
    const int t       = rowhi & 7;
    const int bc      = rowhi >> 3;            // b*3 + c
    const int b       = bc / 3;

    const int bk = b * NKEY + group_id[b * T + t];

    __shared__ float wc[R];
    __shared__ int   off[R];

    const int nnz = g_nnz[bk];                 // uniform, L2-broadcast
    if (tid < nnz) {
        wc[tid]  = g_wc[bk][tid];
        off[tid] = g_off[bk][tid];
    }
    __syncthreads();

    const float* xr = x + (((size_t)bc * T + t) * H + y) * W + lane * 4;

    float4 acc = make_float4(0.f, 0.f, 0.f, 0.f);
    #pragma unroll 4
    for (int i = 0; i < nnz; i++) {
        const float w = wc[i];
        const float4 v = *reinterpret_cast<const float4*>(xr + off[i]);
        acc.x = fmaf(w, v.x, acc.x);
        acc.y = fmaf(w, v.y, acc.y);
        acc.z = fmaf(w, v.z, acc.z);
        acc.w = fmaf(w, v.w, acc.w);
    }

    *reinterpret_cast<float4*>(out + ((size_t)(rowbase + wrp)) * OUTHW + lane * 4) = acc;
}

// ---------------------------------------------------------------------------
// Launch: inputs (metadata order): x, score, noise, sigma, group_id
// Two graph nodes.
// ---------------------------------------------------------------------------
extern "C" void kernel_launch(void* const* d_in, const int* in_sizes, int n_in,
                              void* d_out, int out_size)
{
    const float* x        = (const float*)d_in[0];
    const float* score    = (const float*)d_in[1];
    const float* noise    = (const float*)d_in[2];
    const float* sigma    = (const float*)d_in[3];
    const int*   group_id = (const int*)  d_in[4];
    float*       out      = (float*)d_out;

    argmax_kernel<<<dim3(ABPK, BK), 256>>>(score, noise, sigma);

    const int nblocks = (B * C * T * OUTHW) / 16;   // 384
    gather_kernel<<<nblocks, 512>>>(x, group_id, out);
}